// round 3
// baseline (speedup 1.0000x reference)
#include <cuda_runtime.h>
#include <math.h>

// ---------------- problem constants ----------------
#define B_TOTAL   131072
#define SDIM      137          // state dim
#define AHD       128          // SDIM - ZED - 1
#define ZED       8
#define HID       256
#define NBLK      4
#define STRENGTH  0.1f

// ---------------- tiling ----------------
#define MT        64           // batch-rows per CTA
#define NT        64           // N tile
#define AP        68           // activation buffer pitch (cols = MT + 4 pad)
#define WP        264          // weight tile pitch (K + pad, float4-aligned, bank-friendly)
#define NTHREADS  256

#define SMEM_FLOATS (2*HID*AP + NT*WP)
#define SMEM_BYTES  (SMEM_FLOATS * 4)

// ---------------- precomputed small tensors ----------------
// seq-len-1 attention collapses to a single linear map: softmax over 1 key == 1,
// so output = (x @ Wv^T + bv) @ out_w^T + out_b  ->  x @ (out_w Wv)^T + (out_w bv + out_b)
__device__ float g_Mta[AHD * AHD];
__device__ float g_cta[AHD];
__device__ float g_Mlm[ZED * ZED];
__device__ float g_clm[ZED];
__device__ float g_b0eff[HID];   // b0 + sin(t')*W0[:,137] + cos(t')*W0[:,138]

__global__ void precompute_kernel(const float* __restrict__ t,
                                  const float* __restrict__ W0,
                                  const float* __restrict__ b0,
                                  const float* __restrict__ lm_in_w,
                                  const float* __restrict__ lm_in_b,
                                  const float* __restrict__ lm_out_w,
                                  const float* __restrict__ lm_out_b,
                                  const float* __restrict__ ta_in_w,
                                  const float* __restrict__ ta_in_b,
                                  const float* __restrict__ ta_out_w,
                                  const float* __restrict__ ta_out_b)
{
    int b   = blockIdx.x;
    int tid = threadIdx.x;
    if (b < AHD) {
        // M_ta row b:  M[j][k] = sum_i ta_out_w[j,i] * Wv_ta[i,k],  Wv_ta = ta_in_w rows [2*AHD, 3*AHD)
        int j = b;
        float acc = 0.f;
        for (int i = 0; i < AHD; i++)
            acc += ta_out_w[j * AHD + i] * ta_in_w[(2 * AHD + i) * AHD + tid];
        g_Mta[j * AHD + tid] = acc;
        if (tid == 0) {
            float c = ta_out_b[j];
            for (int i = 0; i < AHD; i++)
                c += ta_out_w[j * AHD + i] * ta_in_b[2 * AHD + i];
            g_cta[j] = c;
        }
    } else if (b == AHD) {
        if (tid < ZED * ZED) {
            int j = tid >> 3, k = tid & 7;
            float acc = 0.f;
            for (int i = 0; i < ZED; i++)
                acc += lm_out_w[j * ZED + i] * lm_in_w[(2 * ZED + i) * ZED + k];
            g_Mlm[tid] = acc;
        }
        if (tid < ZED) {
            int j = tid;
            float c = lm_out_b[j];
            for (int i = 0; i < ZED; i++)
                c += lm_out_w[j * ZED + i] * lm_in_b[2 * ZED + i];
            g_clm[j] = c;
        }
    } else {
        // time features folded into the first-layer bias
        float ang = t[0] * (6.283185307179586f / 24.0f);
        float sv = sinf(ang), cv = cosf(ang);
        for (int n = tid; n < HID; n += blockDim.x)
            g_b0eff[n] = b0[n] + sv * W0[n * (SDIM + 2) + SDIM]
                               + cv * W0[n * (SDIM + 2) + SDIM + 1];
    }
}

// ---------------- GEMM microkernel ----------------
// C[64,64] tile, thread microtile 4(m) x 4(n).
// A is activation buffer stored TRANSPOSED: A[k][m] with pitch AP (float4 over m, conflict-free).
// W is weight tile stored natural [n][k] with pitch WP (reads are warp-broadcast float4 over k).
__device__ __forceinline__ void mm_tile(const float* __restrict__ A4,  // Abuf + tm*4
                                        const float* __restrict__ Wt,
                                        int tn, int Kq,                // Kq = K/4
                                        float acc[4][4])
{
    const float4* w0 = (const float4*)(Wt + (tn * 4 + 0) * WP);
    const float4* w1 = (const float4*)(Wt + (tn * 4 + 1) * WP);
    const float4* w2 = (const float4*)(Wt + (tn * 4 + 2) * WP);
    const float4* w3 = (const float4*)(Wt + (tn * 4 + 3) * WP);
    for (int k4 = 0; k4 < Kq; k4++) {
        float4 b0 = w0[k4], b1 = w1[k4], b2 = w2[k4], b3 = w3[k4];
        const float* B0 = (const float*)&b0;
        const float* B1 = (const float*)&b1;
        const float* B2 = (const float*)&b2;
        const float* B3 = (const float*)&b3;
        const float* Ar = A4 + (k4 * 4) * AP;
#pragma unroll
        for (int kk = 0; kk < 4; kk++) {
            float4 a = *(const float4*)(Ar + kk * AP);
            float x0 = B0[kk], x1 = B1[kk], x2 = B2[kk], x3 = B3[kk];
            acc[0][0] += a.x * x0; acc[1][0] += a.y * x0; acc[2][0] += a.z * x0; acc[3][0] += a.w * x0;
            acc[0][1] += a.x * x1; acc[1][1] += a.y * x1; acc[2][1] += a.z * x1; acc[3][1] += a.w * x1;
            acc[0][2] += a.x * x2; acc[1][2] += a.y * x2; acc[2][2] += a.z * x2; acc[3][2] += a.w * x2;
            acc[0][3] += a.x * x3; acc[1][3] += a.y * x3; acc[2][3] += a.z * x3; acc[3][3] += a.w * x3;
        }
    }
}

// ---------------- fused main kernel ----------------
__global__ __launch_bounds__(NTHREADS, 1)
void fused_odefunc_kernel(const float* __restrict__ state,
                          const float* __restrict__ W0,
                          const float* __restrict__ blkW1,
                          const float* __restrict__ blkb1,
                          const float* __restrict__ blkW2,
                          const float* __restrict__ blkb2,
                          const float* __restrict__ Wout,
                          const float* __restrict__ bout,
                          float* __restrict__ out)
{
    extern __shared__ float sm[];
    float* Hb = sm;                  // h activations, transposed [HID][AP]
    float* Tb = sm + HID * AP;       // temp buffer / state^T
    float* Wt = sm + 2 * HID * AP;   // weight tile [NT][WP]

    const int tid = threadIdx.x;
    const int tm  = tid & 15;        // m sub-tile (x4)
    const int tn  = tid >> 4;        // n sub-tile (x4)
    const int m0  = blockIdx.x * MT;
    const float* A4H = Hb + tm * 4;
    const float* A4T = Tb + tm * 4;

    // ---- load state^T into Tb (rows 137..139 zero-padded for clean K=140 loop) ----
    for (int idx = tid; idx < MT * SDIM; idx += NTHREADS) {
        int m = idx / SDIM;
        int k = idx - m * SDIM;
        Tb[k * AP + m] = state[(size_t)(m0 + m) * SDIM + k];
    }
    for (int idx = tid; idx < 3 * MT; idx += NTHREADS) {
        int k = SDIM + idx / MT;
        int m = idx & (MT - 1);
        Tb[k * AP + m] = 0.f;
    }
    __syncthreads();

    // ---- GEMM0: Hb = relu(x @ W0^T + b0eff), K = 137 (padded to 140) ----
    for (int nt = 0; nt < HID / NT; nt++) {
        int n0 = nt * NT;
        for (int t = tid; t < NT * 140; t += NTHREADS) {   // scalar load, W0 row pitch 139
            int r = t / 140;
            int k = t - r * 140;
            Wt[r * WP + k] = (k < SDIM) ? W0[(n0 + r) * (SDIM + 2) + k] : 0.f;
        }
        __syncthreads();
        float acc[4][4] = {};
        mm_tile(A4T, Wt, tn, 140 / 4, acc);
#pragma unroll
        for (int j = 0; j < 4; j++) {
            int n = n0 + tn * 4 + j;
            float bb = g_b0eff[n];
            float4 v;
            v.x = fmaxf(acc[0][j] + bb, 0.f);
            v.y = fmaxf(acc[1][j] + bb, 0.f);
            v.z = fmaxf(acc[2][j] + bb, 0.f);
            v.w = fmaxf(acc[3][j] + bb, 0.f);
            *(float4*)(Hb + n * AP + tm * 4) = v;
        }
        __syncthreads();
    }

    // ---- 4 residual blocks ----
    for (int blk = 0; blk < NBLK; blk++) {
        const float* W1 = blkW1 + blk * HID * HID;
        const float* W2 = blkW2 + blk * HID * HID;
        const float* b1 = blkb1 + blk * HID;
        const float* b2 = blkb2 + blk * HID;

        // GEMM1: Tb = tanh(Hb @ W1^T + b1)
        for (int nt = 0; nt < HID / NT; nt++) {
            int n0 = nt * NT;
            {
                const float4* src = (const float4*)(W1 + n0 * HID);
#pragma unroll
                for (int it = 0; it < (NT * HID / 4) / NTHREADS; it++) {   // 16
                    int t  = tid + it * NTHREADS;
                    int r  = t >> 6;
                    int c4 = t & 63;
                    *(float4*)(Wt + r * WP + c4 * 4) = src[r * 64 + c4];
                }
            }
            __syncthreads();
            float acc[4][4] = {};
            mm_tile(A4H, Wt, tn, HID / 4, acc);
#pragma unroll
            for (int j = 0; j < 4; j++) {
                int n = n0 + tn * 4 + j;
                float bb = b1[n];
                float4 v;
                v.x = tanhf(acc[0][j] + bb);
                v.y = tanhf(acc[1][j] + bb);
                v.z = tanhf(acc[2][j] + bb);
                v.w = tanhf(acc[3][j] + bb);
                *(float4*)(Tb + n * AP + tm * 4) = v;
            }
            __syncthreads();
        }

        // GEMM2: Hb = tanh(Hb + Tb @ W2^T + b2)
        for (int nt = 0; nt < HID / NT; nt++) {
            int n0 = nt * NT;
            {
                const float4* src = (const float4*)(W2 + n0 * HID);
#pragma unroll
                for (int it = 0; it < (NT * HID / 4) / NTHREADS; it++) {
                    int t  = tid + it * NTHREADS;
                    int r  = t >> 6;
                    int c4 = t & 63;
                    *(float4*)(Wt + r * WP + c4 * 4) = src[r * 64 + c4];
                }
            }
            __syncthreads();
            float acc[4][4] = {};
            mm_tile(A4T, Wt, tn, HID / 4, acc);
#pragma unroll
            for (int j = 0; j < 4; j++) {
                int n = n0 + tn * 4 + j;
                float bb = b2[n];
                float4 old = *(const float4*)(Hb + n * AP + tm * 4);
                float4 v;
                v.x = tanhf(old.x + acc[0][j] + bb);
                v.y = tanhf(old.y + acc[1][j] + bb);
                v.z = tanhf(old.z + acc[2][j] + bb);
                v.w = tanhf(old.w + acc[3][j] + bb);
                *(float4*)(Hb + n * AP + tm * 4) = v;
            }
            __syncthreads();
        }
    }

    // ---- reload state^T (Tb was clobbered by block temps) for the delta path ----
    for (int idx = tid; idx < MT * SDIM; idx += NTHREADS) {
        int m = idx / SDIM;
        int k = idx - m * SDIM;
        Tb[k * AP + m] = state[(size_t)(m0 + m) * SDIM + k];
    }
    __syncthreads();

    // ---- output: core = Hb @ Wout^T + bout, plus STRENGTH * delta ----
    for (int nt = 0; nt < 3; nt++) {
        int n0 = nt * NT;
        {   // Wout tile (zero-fill rows >= 137)
            const float4* src = (const float4*)(Wout);
#pragma unroll
            for (int it = 0; it < (NT * HID / 4) / NTHREADS; it++) {
                int t  = tid + it * NTHREADS;
                int r  = t >> 6;
                int c4 = t & 63;
                float4 v = make_float4(0.f, 0.f, 0.f, 0.f);
                if (n0 + r < SDIM) v = src[(n0 + r) * 64 + c4];
                *(float4*)(Wt + r * WP + c4 * 4) = v;
            }
        }
        __syncthreads();
        float acc[4][4] = {};
        mm_tile(A4H, Wt, tn, HID / 4, acc);
        __syncthreads();   // all threads done with the Wout tile

        if (nt < 2) {
            // delta_h = state[:, :128] @ M_ta^T + c_ta - state[:, :128]
            {
#pragma unroll
                for (int it = 0; it < (NT * AHD / 4) / NTHREADS; it++) {   // 8
                    int t  = tid + it * NTHREADS;
                    int r  = t >> 5;
                    int c4 = t & 31;
                    *(float4*)(Wt + r * WP + c4 * 4) = ((const float4*)g_Mta)[(n0 + r) * 32 + c4];
                }
            }
            __syncthreads();
            float acc2[4][4] = {};
            mm_tile(A4T, Wt, tn, AHD / 4, acc2);
#pragma unroll
            for (int j = 0; j < 4; j++) {
                int n = n0 + tn * 4 + j;
                float bo = bout[n];
                float cc = g_cta[n];
#pragma unroll
                for (int i = 0; i < 4; i++) {
                    int m = tm * 4 + i;
                    float st = Tb[n * AP + m];
                    acc[i][j] = acc[i][j] + bo + STRENGTH * (acc2[i][j] + cc - st);
                }
            }
        } else {
            // columns 128..136: delta_loc via 8x8 M_lm; column 136: no delta
#pragma unroll
            for (int j = 0; j < 4; j++) {
                int n = n0 + tn * 4 + j;
                if (n < SDIM - 1) {
                    int jj = n - AHD;
                    float bo = bout[n];
                    float cc = g_clm[jj];
#pragma unroll
                    for (int i = 0; i < 4; i++) {
                        int m = tm * 4 + i;
                        float d = cc;
#pragma unroll
                        for (int k = 0; k < ZED; k++)
                            d += g_Mlm[jj * ZED + k] * Tb[(AHD + k) * AP + m];
                        acc[i][j] = acc[i][j] + bo + STRENGTH * (d - Tb[n * AP + m]);
                    }
                } else if (n == SDIM - 1) {
                    float bo = bout[n];
#pragma unroll
                    for (int i = 0; i < 4; i++)
                        acc[i][j] += bo;
                }
            }
        }
        __syncthreads();   // Wt free (all delta-tile reads done)

        // stage tile into Wt, then coalesced global store
        int cols = (nt < 2) ? NT : (SDIM - 128);   // 64, 64, 9
#pragma unroll
        for (int j = 0; j < 4; j++) {
            int c = tn * 4 + j;
            if (c < cols) {
#pragma unroll
                for (int i = 0; i < 4; i++)
                    Wt[(tm * 4 + i) * NT + c] = acc[i][j];
            }
        }
        __syncthreads();
        for (int idx = tid; idx < MT * cols; idx += NTHREADS) {
            int m = idx / cols;
            int c = idx - m * cols;
            out[(size_t)(m0 + m) * SDIM + n0 + c] = Wt[m * NT + c];
        }
        __syncthreads();
    }
}

// ---------------- launch ----------------
extern "C" void kernel_launch(void* const* d_in, const int* in_sizes, int n_in,
                              void* d_out, int out_size)
{
    const float* t        = (const float*)d_in[0];
    const float* state    = (const float*)d_in[1];
    const float* W0       = (const float*)d_in[2];
    const float* b0       = (const float*)d_in[3];
    const float* blkW1    = (const float*)d_in[4];
    const float* blkb1    = (const float*)d_in[5];
    const float* blkW2    = (const float*)d_in[6];
    const float* blkb2    = (const float*)d_in[7];
    const float* Wout     = (const float*)d_in[8];
    const float* bout     = (const float*)d_in[9];
    const float* lm_in_w  = (const float*)d_in[10];
    const float* lm_in_b  = (const float*)d_in[11];
    const float* lm_out_w = (const float*)d_in[12];
    const float* lm_out_b = (const float*)d_in[13];
    const float* ta_in_w  = (const float*)d_in[14];
    const float* ta_in_b  = (const float*)d_in[15];
    const float* ta_out_w = (const float*)d_in[16];
    const float* ta_out_b = (const float*)d_in[17];
    float* out = (float*)d_out;

    cudaFuncSetAttribute(fused_odefunc_kernel,
                         cudaFuncAttributeMaxDynamicSharedMemorySize, SMEM_BYTES);

    precompute_kernel<<<AHD + 2, 128>>>(t, W0, b0,
                                        lm_in_w, lm_in_b, lm_out_w, lm_out_b,
                                        ta_in_w, ta_in_b, ta_out_w, ta_out_b);

    fused_odefunc_kernel<<<B_TOTAL / MT, NTHREADS, SMEM_BYTES>>>(
        state, W0, blkW1, blkb1, blkW2, blkb2, Wout, bout, out);
}

// round 5
// speedup vs baseline: 1.3148x; 1.3148x over previous
#include <cuda_runtime.h>
#include <math.h>

// ---------------- problem constants ----------------
#define B_TOTAL   131072
#define SDIM      137
#define AHD       128          // SDIM - ZED - 1
#define ZED       8
#define HID       256
#define NBLK      4
#define STRENGTH  0.1f

// ---------------- tiling ----------------
#define MT        64           // batch-rows per CTA
#define AP        68           // activation pitch (64 + 4 pad), floats
#define KC        32           // K chunk
#define WCH       36           // weight chunk pitch (32 + 4), floats
#define WBUF      (HID * WCH)  // one weight-chunk buffer (all 256 n-rows)
#define NTHREADS  512

#define SMEM_FLOATS (2*HID*AP + 2*WBUF)
#define SMEM_BYTES  (SMEM_FLOATS * 4)

// ---------------- precomputed small tensors ----------------
// seq-len-1 attention collapses to a linear map:
// out = x @ (out_w @ Wv)^T + (out_w @ bv + out_b)
__device__ float g_Mta[AHD * AHD];
__device__ float g_cta[AHD];
__device__ float g_Mlm[ZED * ZED];
__device__ float g_clm[ZED];
__device__ float g_b0eff[HID];

__global__ void precompute_kernel(const float* __restrict__ t,
                                  const float* __restrict__ W0,
                                  const float* __restrict__ b0,
                                  const float* __restrict__ lm_in_w,
                                  const float* __restrict__ lm_in_b,
                                  const float* __restrict__ lm_out_w,
                                  const float* __restrict__ lm_out_b,
                                  const float* __restrict__ ta_in_w,
                                  const float* __restrict__ ta_in_b,
                                  const float* __restrict__ ta_out_w,
                                  const float* __restrict__ ta_out_b)
{
    int b   = blockIdx.x;
    int tid = threadIdx.x;
    if (b < AHD) {
        int j = b;
        float acc = 0.f;
        for (int i = 0; i < AHD; i++)
            acc += ta_out_w[j * AHD + i] * ta_in_w[(2 * AHD + i) * AHD + tid];
        g_Mta[j * AHD + tid] = acc;
        if (tid == 0) {
            float c = ta_out_b[j];
            for (int i = 0; i < AHD; i++)
                c += ta_out_w[j * AHD + i] * ta_in_b[2 * AHD + i];
            g_cta[j] = c;
        }
    } else if (b == AHD) {
        if (tid < ZED * ZED) {
            int j = tid >> 3, k = tid & 7;
            float acc = 0.f;
            for (int i = 0; i < ZED; i++)
                acc += lm_out_w[j * ZED + i] * lm_in_w[(2 * ZED + i) * ZED + k];
            g_Mlm[tid] = acc;
        }
        if (tid < ZED) {
            int j = tid;
            float c = lm_out_b[j];
            for (int i = 0; i < ZED; i++)
                c += lm_out_w[j * ZED + i] * lm_in_b[2 * ZED + i];
            g_clm[j] = c;
        }
    } else {
        float ang = t[0] * (6.283185307179586f / 24.0f);
        float sv = sinf(ang), cv = cosf(ang);
        for (int n = tid; n < HID; n += blockDim.x)
            g_b0eff[n] = b0[n] + sv * W0[n * (SDIM + 2) + SDIM]
                               + cv * W0[n * (SDIM + 2) + SDIM + 1];
    }
}

// ---------------- GEMM microkernel ----------------
// Thread layout: tm = tid&7, tn = tid>>3.
// C cells owned: m in {tm*4+i} U {32+tm*4+i}, n in {tn*4+j}.
// A stored [k][m] pitch AP (two 128B-contiguous float4 groups per warp -> 1 wf each).
// W chunk stored [n][kc] pitch WCH (4 tn values/warp -> near-broadcast).
__device__ __forceinline__ void mm_chunk(const float* __restrict__ Ab,   // Abuf + kbase*AP + tm*4
                                         const float* __restrict__ Wr,   // buf + tn*4*WCH
                                         float (&acc)[8][4])
{
#pragma unroll
    for (int k4 = 0; k4 < KC / 4; k4++) {
        float4 w0 = *(const float4*)(Wr + 0 * WCH + k4 * 4);
        float4 w1 = *(const float4*)(Wr + 1 * WCH + k4 * 4);
        float4 w2 = *(const float4*)(Wr + 2 * WCH + k4 * 4);
        float4 w3 = *(const float4*)(Wr + 3 * WCH + k4 * 4);
        const float* W0v = (const float*)&w0;
        const float* W1v = (const float*)&w1;
        const float* W2v = (const float*)&w2;
        const float* W3v = (const float*)&w3;
#pragma unroll
        for (int kk = 0; kk < 4; kk++) {
            const float* Ar = Ab + (k4 * 4 + kk) * AP;
            float4 a0 = *(const float4*)(Ar);
            float4 a1 = *(const float4*)(Ar + 32);
            float x0 = W0v[kk], x1 = W1v[kk], x2 = W2v[kk], x3 = W3v[kk];
            acc[0][0] += a0.x * x0; acc[1][0] += a0.y * x0; acc[2][0] += a0.z * x0; acc[3][0] += a0.w * x0;
            acc[4][0] += a1.x * x0; acc[5][0] += a1.y * x0; acc[6][0] += a1.z * x0; acc[7][0] += a1.w * x0;
            acc[0][1] += a0.x * x1; acc[1][1] += a0.y * x1; acc[2][1] += a0.z * x1; acc[3][1] += a0.w * x1;
            acc[4][1] += a1.x * x1; acc[5][1] += a1.y * x1; acc[6][1] += a1.z * x1; acc[7][1] += a1.w * x1;
            acc[0][2] += a0.x * x2; acc[1][2] += a0.y * x2; acc[2][2] += a0.z * x2; acc[3][2] += a0.w * x2;
            acc[4][2] += a1.x * x2; acc[5][2] += a1.y * x2; acc[6][2] += a1.z * x2; acc[7][2] += a1.w * x2;
            acc[0][3] += a0.x * x3; acc[1][3] += a0.y * x3; acc[2][3] += a0.z * x3; acc[3][3] += a0.w * x3;
            acc[4][3] += a1.x * x3; acc[5][3] += a1.y * x3; acc[6][3] += a1.z * x3; acc[7][3] += a1.w * x3;
        }
    }
}

// Prefetch one K-chunk (all 256 n-rows x 32 k) into registers. pitch4 = row pitch/4.
// Rows >= Nv are zero-filled.
__device__ __forceinline__ void ld_chunk(const float* __restrict__ src, int pitch4,
                                         int k0, int Nv, float4 (&pf)[4], int tid)
{
    int c4 = tid & 7;
    int r  = tid >> 3;
#pragma unroll
    for (int it = 0; it < 4; it++) {
        int rr = r + it * 64;
        float4 v = make_float4(0.f, 0.f, 0.f, 0.f);
        if (rr < Nv) v = ((const float4*)src)[rr * pitch4 + (k0 >> 2) + c4];
        pf[it] = v;
    }
}

__device__ __forceinline__ void st_chunk(float* __restrict__ buf, const float4 (&pf)[4], int tid)
{
    int c4 = tid & 7;
    int r  = tid >> 3;
#pragma unroll
    for (int it = 0; it < 4; it++)
        *(float4*)(buf + (r + it * 64) * WCH + c4 * 4) = pf[it];
}

// Full K-loop GEMM with double-buffered weight chunks.
__device__ __forceinline__ void gemm_chunks(const float* __restrict__ W, int pitch4, int Nv,
                                            int nchunks,
                                            const float* __restrict__ Abuf,
                                            float* __restrict__ Wt,
                                            int tid, int tm, int tn,
                                            float (&acc)[8][4])
{
    float4 pf[4];
    ld_chunk(W, pitch4, 0, Nv, pf, tid);
    __syncthreads();                 // previous users of Wt / activation writers done
    st_chunk(Wt, pf, tid);
    __syncthreads();
    for (int c = 0; c < nchunks; c++) {
        if (c + 1 < nchunks) ld_chunk(W, pitch4, (c + 1) * KC, Nv, pf, tid);
        mm_chunk(Abuf + c * KC * AP + tm * 4, Wt + (c & 1) * WBUF + tn * 4 * WCH, acc);
        if (c + 1 < nchunks) st_chunk(Wt + ((c + 1) & 1) * WBUF, pf, tid);
        __syncthreads();
    }
}

// ---------------- fused main kernel ----------------
__global__ __launch_bounds__(NTHREADS, 1)
void fused_odefunc_kernel(const float* __restrict__ state,
                          const float* __restrict__ W0,
                          const float* __restrict__ blkW1,
                          const float* __restrict__ blkb1,
                          const float* __restrict__ blkW2,
                          const float* __restrict__ blkb2,
                          const float* __restrict__ Wout,
                          const float* __restrict__ bout,
                          float* __restrict__ out)
{
    extern __shared__ float sm[];
    float* Hb = sm;                  // h activations, transposed [HID][AP]
    float* Tb = sm + HID * AP;       // temps / state^T
    float* Wt = sm + 2 * HID * AP;   // weight chunk double buffer (2 x WBUF)

    const int tid = threadIdx.x;
    const int tm  = tid & 7;
    const int tn  = tid >> 3;        // 0..63
    const int m0  = blockIdx.x * MT;

    // ---- load state^T into Tb; zero rows 137..159 for the padded K=160 GEMM0 ----
    for (int idx = tid; idx < MT * SDIM; idx += NTHREADS) {
        int m = idx / SDIM;
        int k = idx - m * SDIM;
        Tb[k * AP + m] = state[(size_t)(m0 + m) * SDIM + k];
    }
    for (int idx = tid; idx < MT * 23; idx += NTHREADS) {
        int k = SDIM + (idx >> 6);
        int m = idx & 63;
        Tb[k * AP + m] = 0.f;
    }

    float acc[8][4];

    // ---- GEMM0: Hb = relu(x @ W0^T + b0eff), K padded to 160, scalar loads (pitch 139) ----
#pragma unroll
    for (int mi = 0; mi < 8; mi++)
#pragma unroll
        for (int j = 0; j < 4; j++) acc[mi][j] = 0.f;
    for (int c = 0; c < 5; c++) {
        __syncthreads();             // prior mm readers of Wt (and state writers at c=0) done
        int k0 = c * KC;
        for (int idx = tid; idx < HID * KC; idx += NTHREADS) {
            int r  = idx >> 5;
            int cc = idx & 31;
            int col = k0 + cc;
            Wt[r * WCH + cc] = (col < SDIM) ? W0[r * (SDIM + 2) + col] : 0.f;
        }
        __syncthreads();
        mm_chunk(Tb + c * KC * AP + tm * 4, Wt + tn * 4 * WCH, acc);
    }
#pragma unroll
    for (int j = 0; j < 4; j++) {
        int n = tn * 4 + j;
        float bb = g_b0eff[n];
        float4 v0, v1;
        v0.x = fmaxf(acc[0][j] + bb, 0.f); v0.y = fmaxf(acc[1][j] + bb, 0.f);
        v0.z = fmaxf(acc[2][j] + bb, 0.f); v0.w = fmaxf(acc[3][j] + bb, 0.f);
        v1.x = fmaxf(acc[4][j] + bb, 0.f); v1.y = fmaxf(acc[5][j] + bb, 0.f);
        v1.z = fmaxf(acc[6][j] + bb, 0.f); v1.w = fmaxf(acc[7][j] + bb, 0.f);
        *(float4*)(Hb + n * AP + tm * 4)      = v0;
        *(float4*)(Hb + n * AP + 32 + tm * 4) = v1;
    }

    // ---- 4 residual blocks ----
    for (int blk = 0; blk < NBLK; blk++) {
        const float* W1 = blkW1 + blk * HID * HID;
        const float* W2 = blkW2 + blk * HID * HID;
        const float* b1 = blkb1 + blk * HID;
        const float* b2 = blkb2 + blk * HID;

        // Tb = tanh(Hb @ W1^T + b1)
#pragma unroll
        for (int mi = 0; mi < 8; mi++)
#pragma unroll
            for (int j = 0; j < 4; j++) acc[mi][j] = 0.f;
        gemm_chunks(W1, HID / 4, HID, HID / KC, Hb, Wt, tid, tm, tn, acc);
#pragma unroll
        for (int j = 0; j < 4; j++) {
            int n = tn * 4 + j;
            float bb = b1[n];
            float4 v0, v1;
            v0.x = tanhf(acc[0][j] + bb); v0.y = tanhf(acc[1][j] + bb);
            v0.z = tanhf(acc[2][j] + bb); v0.w = tanhf(acc[3][j] + bb);
            v1.x = tanhf(acc[4][j] + bb); v1.y = tanhf(acc[5][j] + bb);
            v1.z = tanhf(acc[6][j] + bb); v1.w = tanhf(acc[7][j] + bb);
            *(float4*)(Tb + n * AP + tm * 4)      = v0;
            *(float4*)(Tb + n * AP + 32 + tm * 4) = v1;
        }

        // Hb = tanh(Hb + Tb @ W2^T + b2)
#pragma unroll
        for (int mi = 0; mi < 8; mi++)
#pragma unroll
            for (int j = 0; j < 4; j++) acc[mi][j] = 0.f;
        gemm_chunks(W2, HID / 4, HID, HID / KC, Tb, Wt, tid, tm, tn, acc);
#pragma unroll
        for (int j = 0; j < 4; j++) {
            int n = tn * 4 + j;
            float bb = b2[n];
            float4 o0 = *(const float4*)(Hb + n * AP + tm * 4);
            float4 o1 = *(const float4*)(Hb + n * AP + 32 + tm * 4);
            float4 v0, v1;
            v0.x = tanhf(o0.x + acc[0][j] + bb); v0.y = tanhf(o0.y + acc[1][j] + bb);
            v0.z = tanhf(o0.z + acc[2][j] + bb); v0.w = tanhf(o0.w + acc[3][j] + bb);
            v1.x = tanhf(o1.x + acc[4][j] + bb); v1.y = tanhf(o1.y + acc[5][j] + bb);
            v1.z = tanhf(o1.z + acc[6][j] + bb); v1.w = tanhf(o1.w + acc[7][j] + bb);
            *(float4*)(Hb + n * AP + tm * 4)      = v0;
            *(float4*)(Hb + n * AP + 32 + tm * 4) = v1;
        }
    }

    // ---- reload state^T into Tb (rows 0..136) for the delta path ----
    for (int idx = tid; idx < MT * SDIM; idx += NTHREADS) {
        int m = idx / SDIM;
        int k = idx - m * SDIM;
        Tb[k * AP + m] = state[(size_t)(m0 + m) * SDIM + k];
    }

    // ---- core = Hb @ Wout^T (rows >= 137 zero-filled) ----
#pragma unroll
    for (int mi = 0; mi < 8; mi++)
#pragma unroll
        for (int j = 0; j < 4; j++) acc[mi][j] = 0.f;
    gemm_chunks(Wout, HID / 4, SDIM, HID / KC, Hb, Wt, tid, tm, tn, acc);

    // ---- delta_h GEMM: acc2 = state[:, :128] @ M_ta^T (n >= 128 rows zero) ----
    float acc2[8][4];
#pragma unroll
    for (int mi = 0; mi < 8; mi++)
#pragma unroll
        for (int j = 0; j < 4; j++) acc2[mi][j] = 0.f;
    gemm_chunks(g_Mta, AHD / 4, AHD, AHD / KC, Tb, Wt, tid, tm, tn, acc2);

    // ---- combine + stage + store ----
    float* stage = Wt;               // 64 x 140 floats, fits in the 2*WBUF area
#pragma unroll
    for (int j = 0; j < 4; j++) {
        int n = tn * 4 + j;
        if (n >= SDIM) continue;
        float bo = bout[n];
#pragma unroll
        for (int mi = 0; mi < 8; mi++) {
            int m = (mi < 4) ? (tm * 4 + mi) : (32 + tm * 4 + (mi - 4));
            float val;
            if (n < AHD) {
                float st = Tb[n * AP + m];
                val = acc[mi][j] + bo + STRENGTH * (acc2[mi][j] + g_cta[n] - st);
            } else if (n < SDIM - 1) {
                int jj = n - AHD;
                float d = g_clm[jj];
#pragma unroll
                for (int k = 0; k < ZED; k++)
                    d += g_Mlm[jj * ZED + k] * Tb[(AHD + k) * AP + m];
                val = acc[mi][j] + bo + STRENGTH * (d - Tb[n * AP + m]);
            } else {
                val = acc[mi][j] + bo;
            }
            stage[m * 140 + n] = val;
        }
    }
    __syncthreads();
    for (int idx = tid; idx < MT * SDIM; idx += NTHREADS) {
        int m = idx / SDIM;
        int c = idx - m * SDIM;
        out[(size_t)(m0 + m) * SDIM + c] = stage[m * 140 + c];
    }
}

// ---------------- launch ----------------
extern "C" void kernel_launch(void* const* d_in, const int* in_sizes, int n_in,
                              void* d_out, int out_size)
{
    const float* t        = (const float*)d_in[0];
    const float* state    = (const float*)d_in[1];
    const float* W0       = (const float*)d_in[2];
    const float* b0       = (const float*)d_in[3];
    const float* blkW1    = (const float*)d_in[4];
    const float* blkb1    = (const float*)d_in[5];
    const float* blkW2    = (const float*)d_in[6];
    const float* blkb2    = (const float*)d_in[7];
    const float* Wout     = (const float*)d_in[8];
    const float* bout     = (const float*)d_in[9];
    const float* lm_in_w  = (const float*)d_in[10];
    const float* lm_in_b  = (const float*)d_in[11];
    const float* lm_out_w = (const float*)d_in[12];
    const float* lm_out_b = (const float*)d_in[13];
    const float* ta_in_w  = (const float*)d_in[14];
    const float* ta_in_b  = (const float*)d_in[15];
    const float* ta_out_w = (const float*)d_in[16];
    const float* ta_out_b = (const float*)d_in[17];
    float* out = (float*)d_out;

    cudaFuncSetAttribute(fused_odefunc_kernel,
                         cudaFuncAttributeMaxDynamicSharedMemorySize, SMEM_BYTES);

    precompute_kernel<<<AHD + 2, 128>>>(t, W0, b0,
                                        lm_in_w, lm_in_b, lm_out_w, lm_out_b,
                                        ta_in_w, ta_in_b, ta_out_w, ta_out_b);

    fused_odefunc_kernel<<<B_TOTAL / MT, NTHREADS, SMEM_BYTES>>>(
        state, W0, blkW1, blkb1, blkW2, blkb2, Wout, bout, out);
}

// round 13
// speedup vs baseline: 1.4376x; 1.0934x over previous
#include <cuda_runtime.h>
#include <math.h>

// ---------------- problem constants ----------------
#define B_TOTAL   131072
#define SDIM      137
#define AHD       128          // SDIM - ZED - 1
#define ZED       8
#define HID       256
#define NBLK      4
#define STRENGTH  0.1f

// ---------------- tiling ----------------
#define MT        64           // batch-rows per CTA
#define AP        68           // activation pitch (64 + 4 pad), floats
#define KC        32           // K chunk
#define WCH       36           // weight chunk row pitch (32 + 4), floats
#define WBUF      (HID * WCH)  // one weight-chunk buffer
#define NTHREADS  256

#define SMEM_FLOATS (2*HID*AP + 2*WBUF)
#define SMEM_BYTES  (SMEM_FLOATS * 4)

typedef unsigned long long ull;

// XOR swizzle of the 16B group WITHIN a 36-word row (never overlaps rows):
// word offset of group g in row r = r*WCH + ((g ^ ((r>>3)&7)) << 2)
__device__ __forceinline__ int wgrp(int r, int g) {
    return r * WCH + (((g ^ ((r >> 3) & 7))) << 2);
}

// ---------------- f32x2 helpers (FFMA2 — ptxas never emits it from C++) ----
__device__ __forceinline__ ull fma2(ull a, ull b, ull c) {
    ull d;
    asm("fma.rn.f32x2 %0, %1, %2, %3;" : "=l"(d) : "l"(a), "l"(b), "l"(c));
    return d;
}
__device__ __forceinline__ ull dup2(float w) {
    ull d;
    unsigned int u = __float_as_uint(w);
    asm("mov.b64 %0, {%1, %1};" : "=l"(d) : "r"(u));
    return d;
}
__device__ __forceinline__ float2 unpk(ull v) {
    float2 f;
    f.x = __uint_as_float((unsigned int)v);
    f.y = __uint_as_float((unsigned int)(v >> 32));
    return f;
}

// ---------------- precomputed small tensors ----------------
// seq-len-1 attention collapses to a linear map:
// out = x @ (out_w @ Wv)^T + (out_w @ bv + out_b)
__device__ float g_Mta[AHD * AHD];
__device__ float g_cta[AHD];
__device__ float g_Mlm[ZED * ZED];
__device__ float g_clm[ZED];
__device__ float g_b0eff[HID];

__global__ void precompute_kernel(const float* __restrict__ t,
                                  const float* __restrict__ W0,
                                  const float* __restrict__ b0,
                                  const float* __restrict__ lm_in_w,
                                  const float* __restrict__ lm_in_b,
                                  const float* __restrict__ lm_out_w,
                                  const float* __restrict__ lm_out_b,
                                  const float* __restrict__ ta_in_w,
                                  const float* __restrict__ ta_in_b,
                                  const float* __restrict__ ta_out_w,
                                  const float* __restrict__ ta_out_b)
{
    int b   = blockIdx.x;
    int tid = threadIdx.x;
    if (b < AHD) {
        int j = b;
        float acc = 0.f;
        for (int i = 0; i < AHD; i++)
            acc += ta_out_w[j * AHD + i] * ta_in_w[(2 * AHD + i) * AHD + tid];
        g_Mta[j * AHD + tid] = acc;
        if (tid == 0) {
            float c = ta_out_b[j];
            for (int i = 0; i < AHD; i++)
                c += ta_out_w[j * AHD + i] * ta_in_b[2 * AHD + i];
            g_cta[j] = c;
        }
    } else if (b == AHD) {
        if (tid < ZED * ZED) {
            int j = tid >> 3, k = tid & 7;
            float acc = 0.f;
            for (int i = 0; i < ZED; i++)
                acc += lm_out_w[j * ZED + i] * lm_in_w[(2 * ZED + i) * ZED + k];
            g_Mlm[tid] = acc;
        }
        if (tid < ZED) {
            int j = tid;
            float c = lm_out_b[j];
            for (int i = 0; i < ZED; i++)
                c += lm_out_w[j * ZED + i] * lm_in_b[2 * ZED + i];
            g_clm[j] = c;
        }
    } else {
        float ang = t[0] * (6.283185307179586f / 24.0f);
        float sv = sinf(ang), cv = cosf(ang);
        for (int n = tid; n < HID; n += blockDim.x)
            g_b0eff[n] = b0[n] + sv * W0[n * (SDIM + 2) + SDIM]
                               + cv * W0[n * (SDIM + 2) + SDIM + 1];
    }
}

// ---------------- GEMM microkernel ----------------
// 256 threads: tm = tid&7, tn = tid>>3 (0..31).
// C cells per thread: m in {tm*4+i} U {32+tm*4+i} (as 4 f32x2 pairs), n in {tn*8+j}.
// A stored [k][m] pitch AP; loaded as double2 (16B), halves ARE the f32x2 pairs.
// W chunk stored [n][k] pitch WCH with XOR group swizzle; broadcast across the 4
// tn-lanes of a warp, duplicated into both f32x2 lanes via mov.b64.
__device__ __forceinline__ void mm_chunk(const float* __restrict__ Ab,   // Abuf + kbase*AP + tm*4
                                         const float* __restrict__ Wr,   // Wt(+buf) + tn*8*WCH
                                         int xk,                         // tn & 7
                                         ull (&acc)[4][8])
{
#pragma unroll
    for (int k4 = 0; k4 < KC / 4; k4++) {
        const int koff = ((k4 ^ xk) << 2);
        float4 w[8];
#pragma unroll
        for (int j = 0; j < 8; j++)
            w[j] = *(const float4*)(Wr + j * WCH + koff);
#pragma unroll
        for (int kk = 0; kk < 4; kk++) {
            const float* Ar = Ab + (k4 * 4 + kk) * AP;
            double2 a0 = *(const double2*)(Ar);
            double2 a1 = *(const double2*)(Ar + 32);
            ull ap0 = __double_as_longlong(a0.x);
            ull ap1 = __double_as_longlong(a0.y);
            ull ap2 = __double_as_longlong(a1.x);
            ull ap3 = __double_as_longlong(a1.y);
#pragma unroll
            for (int j = 0; j < 8; j++) {
                float wv = (kk == 0) ? w[j].x : (kk == 1) ? w[j].y : (kk == 2) ? w[j].z : w[j].w;
                ull wd = dup2(wv);
                acc[0][j] = fma2(ap0, wd, acc[0][j]);
                acc[1][j] = fma2(ap1, wd, acc[1][j]);
                acc[2][j] = fma2(ap2, wd, acc[2][j]);
                acc[3][j] = fma2(ap3, wd, acc[3][j]);
            }
        }
    }
}

// Prefetch one K-chunk (256 n-rows x 32 k) into registers. pitch4 = row pitch/4.
__device__ __forceinline__ void ld_chunk(const float* __restrict__ src, int pitch4,
                                         int k0, int Nv, float4 (&pf)[8], int tid)
{
    int c4 = tid & 7;
    int r  = tid >> 3;          // 0..31
#pragma unroll
    for (int it = 0; it < 8; it++) {
        int rr = r + it * 32;
        float4 v = make_float4(0.f, 0.f, 0.f, 0.f);
        if (rr < Nv) v = ((const float4*)src)[rr * pitch4 + (k0 >> 2) + c4];
        pf[it] = v;
    }
}

__device__ __forceinline__ void st_chunk(float* __restrict__ buf, const float4 (&pf)[8], int tid)
{
    int c4 = tid & 7;
    int r  = tid >> 3;
#pragma unroll
    for (int it = 0; it < 8; it++)
        *(float4*)(buf + wgrp(r + it * 32, c4)) = pf[it];
}

// Full K-loop GEMM with double-buffered weight chunks.
__device__ __forceinline__ void gemm_chunks(const float* __restrict__ W, int pitch4, int Nv,
                                            int nchunks,
                                            const float* __restrict__ Abuf,
                                            float* __restrict__ Wt,
                                            int tid, int tm, int wtb, int xk,
                                            ull (&acc)[4][8])
{
    float4 pf[8];
    ld_chunk(W, pitch4, 0, Nv, pf, tid);
    __syncthreads();                 // previous users of Wt / activation writers done
    st_chunk(Wt, pf, tid);
    __syncthreads();
    for (int c = 0; c < nchunks; c++) {
        if (c + 1 < nchunks) ld_chunk(W, pitch4, (c + 1) * KC, Nv, pf, tid);
        mm_chunk(Abuf + c * KC * AP + tm * 4, Wt + (c & 1) * WBUF + wtb, xk, acc);
        if (c + 1 < nchunks) st_chunk(Wt + ((c + 1) & 1) * WBUF, pf, tid);
        __syncthreads();
    }
}

#define ZACC(A) do { _Pragma("unroll") for (int _p = 0; _p < 4; _p++) _Pragma("unroll") for (int _j = 0; _j < 8; _j++) (A)[_p][_j] = 0ull; } while (0)

// ---------------- fused main kernel ----------------
__global__ __launch_bounds__(NTHREADS, 1)
void fused_odefunc_kernel(const float* __restrict__ state,
                          const float* __restrict__ W0,
                          const float* __restrict__ blkW1,
                          const float* __restrict__ blkb1,
                          const float* __restrict__ blkW2,
                          const float* __restrict__ blkb2,
                          const float* __restrict__ Wout,
                          const float* __restrict__ bout,
                          float* __restrict__ out)
{
    extern __shared__ float sm[];
    float* Hb = sm;                  // h activations, transposed [HID][AP]
    float* Tb = sm + HID * AP;       // temps / state^T
    float* Wt = sm + 2 * HID * AP;   // weight chunk double buffer (2 x WBUF)

    const int tid = threadIdx.x;
    const int tm  = tid & 7;
    const int tn  = tid >> 3;        // 0..31, n base = tn*8
    const int wtb = tn * 8 * WCH;    // thread's W row-base offset inside a chunk
    const int xk  = tn & 7;          // XOR key for group swizzle
    const int m0  = blockIdx.x * MT;

    // ---- load state^T into Tb; zero rows 137..159 for the padded K=160 GEMM0 ----
    for (int idx = tid; idx < MT * SDIM; idx += NTHREADS) {
        int m = idx / SDIM;
        int k = idx - m * SDIM;
        Tb[k * AP + m] = state[(size_t)(m0 + m) * SDIM + k];
    }
    for (int idx = tid; idx < MT * 23; idx += NTHREADS) {
        int k = SDIM + (idx >> 6);
        int m = idx & 63;
        Tb[k * AP + m] = 0.f;
    }

    ull acc[4][8];

    // ---- GEMM0: Hb = relu(x @ W0^T + b0eff), K padded to 160 (W0 pitch 139) ----
    ZACC(acc);
    for (int c = 0; c < 5; c++) {
        __syncthreads();             // prior mm readers of Wt (and state writers at c=0) done
        int k0 = c * KC;
        for (int idx = tid; idx < HID * KC; idx += NTHREADS) {
            int r  = idx >> 5;
            int cc = idx & 31;
            int col = k0 + cc;
            Wt[wgrp(r, cc >> 2) + (cc & 3)] = (col < SDIM) ? W0[r * (SDIM + 2) + col] : 0.f;
        }
        __syncthreads();
        mm_chunk(Tb + c * KC * AP + tm * 4, Wt + wtb, xk, acc);
    }
#pragma unroll
    for (int j = 0; j < 8; j++) {
        int n = tn * 8 + j;
        float bb = g_b0eff[n];
        float2 p0 = unpk(acc[0][j]), p1 = unpk(acc[1][j]);
        float2 p2 = unpk(acc[2][j]), p3 = unpk(acc[3][j]);
        float4 v0 = make_float4(fmaxf(p0.x + bb, 0.f), fmaxf(p0.y + bb, 0.f),
                                fmaxf(p1.x + bb, 0.f), fmaxf(p1.y + bb, 0.f));
        float4 v1 = make_float4(fmaxf(p2.x + bb, 0.f), fmaxf(p2.y + bb, 0.f),
                                fmaxf(p3.x + bb, 0.f), fmaxf(p3.y + bb, 0.f));
        *(float4*)(Hb + n * AP + tm * 4)      = v0;
        *(float4*)(Hb + n * AP + 32 + tm * 4) = v1;
    }

    // ---- 4 residual blocks ----
    for (int blk = 0; blk < NBLK; blk++) {
        const float* W1 = blkW1 + blk * HID * HID;
        const float* W2 = blkW2 + blk * HID * HID;
        const float* b1 = blkb1 + blk * HID;
        const float* b2 = blkb2 + blk * HID;

        // Tb = tanh(Hb @ W1^T + b1)
        ZACC(acc);
        gemm_chunks(W1, HID / 4, HID, HID / KC, Hb, Wt, tid, tm, wtb, xk, acc);
#pragma unroll
        for (int j = 0; j < 8; j++) {
            int n = tn * 8 + j;
            float bb = b1[n];
            float2 p0 = unpk(acc[0][j]), p1 = unpk(acc[1][j]);
            float2 p2 = unpk(acc[2][j]), p3 = unpk(acc[3][j]);
            float4 v0 = make_float4(tanhf(p0.x + bb), tanhf(p0.y + bb),
                                    tanhf(p1.x + bb), tanhf(p1.y + bb));
            float4 v1 = make_float4(tanhf(p2.x + bb), tanhf(p2.y + bb),
                                    tanhf(p3.x + bb), tanhf(p3.y + bb));
            *(float4*)(Tb + n * AP + tm * 4)      = v0;
            *(float4*)(Tb + n * AP + 32 + tm * 4) = v1;
        }

        // Hb = tanh(Hb + Tb @ W2^T + b2)
        ZACC(acc);
        gemm_chunks(W2, HID / 4, HID, HID / KC, Tb, Wt, tid, tm, wtb, xk, acc);
#pragma unroll
        for (int j = 0; j < 8; j++) {
            int n = tn * 8 + j;
            float bb = b2[n];
            float2 p0 = unpk(acc[0][j]), p1 = unpk(acc[1][j]);
            float2 p2 = unpk(acc[2][j]), p3 = unpk(acc[3][j]);
            float4 o0 = *(const float4*)(Hb + n * AP + tm * 4);
            float4 o1 = *(const float4*)(Hb + n * AP + 32 + tm * 4);
            float4 v0 = make_float4(tanhf(o0.x + p0.x + bb), tanhf(o0.y + p0.y + bb),
                                    tanhf(o0.z + p1.x + bb), tanhf(o0.w + p1.y + bb));
            float4 v1 = make_float4(tanhf(o1.x + p2.x + bb), tanhf(o1.y + p2.y + bb),
                                    tanhf(o1.z + p3.x + bb), tanhf(o1.w + p3.y + bb));
            *(float4*)(Hb + n * AP + tm * 4)      = v0;
            *(float4*)(Hb + n * AP + 32 + tm * 4) = v1;
        }
    }

    // ---- reload state^T into Tb (rows 0..136) for the delta path ----
    for (int idx = tid; idx < MT * SDIM; idx += NTHREADS) {
        int m = idx / SDIM;
        int k = idx - m * SDIM;
        Tb[k * AP + m] = state[(size_t)(m0 + m) * SDIM + k];
    }

    // ---- core = Hb @ Wout^T + bout (rows >= 137 zero-filled) ----
    ZACC(acc);
    gemm_chunks(Wout, HID / 4, SDIM, HID / KC, Hb, Wt, tid, tm, wtb, xk, acc);

    // park core(+bout) in Hb (activations are dead) to free registers
#pragma unroll
    for (int j = 0; j < 8; j++) {
        int n = tn * 8 + j;
        float bo = (n < SDIM) ? bout[n] : 0.f;
        float2 p0 = unpk(acc[0][j]), p1 = unpk(acc[1][j]);
        float2 p2 = unpk(acc[2][j]), p3 = unpk(acc[3][j]);
        float4 v0 = make_float4(p0.x + bo, p0.y + bo, p1.x + bo, p1.y + bo);
        float4 v1 = make_float4(p2.x + bo, p2.y + bo, p3.x + bo, p3.y + bo);
        *(float4*)(Hb + n * AP + tm * 4)      = v0;
        *(float4*)(Hb + n * AP + 32 + tm * 4) = v1;
    }

    // ---- delta_h GEMM: acc = state[:, :128] @ M_ta^T (n >= 128 rows zero) ----
    ZACC(acc);
    gemm_chunks(g_Mta, AHD / 4, AHD, AHD / KC, Tb, Wt, tid, tm, wtb, xk, acc);

    // ---- combine + stage + store ----
    float* stage = Wt;               // 64 x 140 floats fits in 2*WBUF
#pragma unroll
    for (int j = 0; j < 8; j++) {
        int n = tn * 8 + j;
        if (n >= SDIM) continue;
        float2 q0 = unpk(acc[0][j]), q1 = unpk(acc[1][j]);
        float2 q2 = unpk(acc[2][j]), q3 = unpk(acc[3][j]);
        float dv[8] = { q0.x, q0.y, q1.x, q1.y, q2.x, q2.y, q3.x, q3.y };
#pragma unroll
        for (int mi = 0; mi < 8; mi++) {
            int m = (mi < 4) ? (tm * 4 + mi) : (32 + tm * 4 + (mi - 4));
            float core = Hb[n * AP + m];
            float val;
            if (n < AHD) {
                val = core + STRENGTH * (dv[mi] + g_cta[n] - Tb[n * AP + m]);
            } else if (n < SDIM - 1) {
                int jj = n - AHD;
                float d = g_clm[jj];
#pragma unroll
                for (int k = 0; k < ZED; k++)
                    d += g_Mlm[jj * ZED + k] * Tb[(AHD + k) * AP + m];
                val = core + STRENGTH * (d - Tb[n * AP + m]);
            } else {
                val = core;
            }
            stage[m * 140 + n] = val;
        }
    }
    __syncthreads();
    for (int idx = tid; idx < MT * SDIM; idx += NTHREADS) {
        int m = idx / SDIM;
        int c = idx - m * SDIM;
        out[(size_t)(m0 + m) * SDIM + c] = stage[m * 140 + c];
    }
}

// ---------------- launch ----------------
extern "C" void kernel_launch(void* const* d_in, const int* in_sizes, int n_in,
                              void* d_out, int out_size)
{
    const float* t        = (const float*)d_in[0];
    const float* state    = (const float*)d_in[1];
    const float* W0       = (const float*)d_in[2];
    const float* b0       = (const float*)d_in[3];
    const float* blkW1    = (const float*)d_in[4];
    const float* blkb1    = (const float*)d_in[5];
    const float* blkW2    = (const float*)d_in[6];
    const float* blkb2    = (const float*)d_in[7];
    const float* Wout     = (const float*)d_in[8];
    const float* bout     = (const float*)d_in[9];
    const float* lm_in_w  = (const float*)d_in[10];
    const float* lm_in_b  = (const float*)d_in[11];
    const float* lm_out_w = (const float*)d_in[12];
    const float* lm_out_b = (const float*)d_in[13];
    const float* ta_in_w  = (const float*)d_in[14];
    const float* ta_in_b  = (const float*)d_in[15];
    const float* ta_out_w = (const float*)d_in[16];
    const float* ta_out_b = (const float*)d_in[17];
    float* out = (float*)d_out;

    cudaFuncSetAttribute(fused_odefunc_kernel,
                         cudaFuncAttributeMaxDynamicSharedMemorySize, SMEM_BYTES);

    precompute_kernel<<<AHD + 2, 128>>>(t, W0, b0,
                                        lm_in_w, lm_in_b, lm_out_w, lm_out_b,
                                        ta_in_w, ta_in_b, ta_out_w, ta_out_b);

    fused_odefunc_kernel<<<B_TOTAL / MT, NTHREADS, SMEM_BYTES>>>(
        state, W0, blkW1, blkb1, blkW2, blkb2, Wout, bout, out);
}